// round 1
// baseline (speedup 1.0000x reference)
#include <cuda_runtime.h>
#include <math.h>
#include <stdint.h>

#define Bn 8192
#define Tn 5
#define Fn 923
#define Hn 64
#define Gn 256
#define EPSc 1e-5f

// ---------------- scratch layout in one big device buffer ----------------
constexpr size_t SZ_H  = (size_t)Bn * Hn;
constexpr size_t SZ_BF = (size_t)Bn * Fn;

constexpr size_t O_H       = 0;
constexpr size_t O_C       = O_H + SZ_H;
constexpr size_t O_GAM     = O_C + SZ_H;
constexpr size_t O_HP      = O_GAM + SZ_H;
constexpr size_t O_YH      = O_HP + SZ_H;
constexpr size_t O_IY      = O_YH + (size_t)Bn * 2;
constexpr size_t O_XH      = O_IY + (size_t)Bn * 2;
constexpr size_t O_XC      = O_XH + SZ_BF;
constexpr size_t O_CTX     = O_XC + SZ_BF;
constexpr size_t O_GATES   = O_CTX + SZ_BF;
constexpr size_t O_ENC     = O_GATES + (size_t)Bn * Gn;
constexpr size_t O_ENCP    = O_ENC + (size_t)Bn * Tn * Fn;
constexpr size_t O_TDWT    = O_ENCP + (size_t)Bn * Tn * Hn;
constexpr size_t O_HISTWT  = O_TDWT + (size_t)Fn * Hn;
constexpr size_t O_ENCWT   = O_HISTWT + (size_t)Hn * Fn;
constexpr size_t O_RNNWIHT = O_ENCWT + (size_t)Hn * Fn;
constexpr size_t O_RNNWHHT = O_RNNWIHT + (size_t)2 * Fn * Gn;
constexpr size_t O_DECWIHT = O_RNNWHHT + (size_t)Hn * Gn;
constexpr size_t O_DECWHHT = O_DECWIHT + (size_t)(Fn + 2) * Gn;
constexpr size_t O_ATTWT   = O_DECWHHT + (size_t)Hn * Gn;
constexpr size_t O_ACC     = O_ATTWT + (size_t)(Fn + Hn) * Hn;
constexpr size_t TOTAL_FLOATS = O_ACC + 16;

static __device__ float g_buf[TOTAL_FLOATS];

// ---------------- helpers ----------------
__device__ __forceinline__ float sigmoidf_(float x) { return 1.0f / (1.0f + expf(-x)); }
__device__ __forceinline__ float rnd6(float v) { return rintf(v * 1e6f) / 1e6f; }

__device__ __forceinline__ void block_reduce2_atomic(float v0, float v1, float* a0, float* a1) {
    __shared__ float s0[32], s1[32];
    int lane = threadIdx.x & 31, w = threadIdx.x >> 5;
#pragma unroll
    for (int o = 16; o; o >>= 1) {
        v0 += __shfl_down_sync(0xffffffffu, v0, o);
        v1 += __shfl_down_sync(0xffffffffu, v1, o);
    }
    if (lane == 0) { s0[w] = v0; s1[w] = v1; }
    __syncthreads();
    if (w == 0) {
        int nw = (blockDim.x + 31) >> 5;
        v0 = (lane < nw) ? s0[lane] : 0.0f;
        v1 = (lane < nw) ? s1[lane] : 0.0f;
#pragma unroll
        for (int o = 16; o; o >>= 1) {
            v0 += __shfl_down_sync(0xffffffffu, v0, o);
            v1 += __shfl_down_sync(0xffffffffu, v1, o);
        }
        if (lane == 0) { atomicAdd(a0, v0); atomicAdd(a1, v1); }
    }
}

// ---------------- kernels ----------------
__global__ void k_zero(float* p, size_t n) {
    size_t i = (size_t)blockIdx.x * blockDim.x + threadIdx.x;
    if (i < n) p[i] = 0.0f;
}

// Wt[c*rows + r] = W[r*cols + c]   (W is [rows, cols])
__global__ void k_transpose(const float* __restrict__ W, float* __restrict__ Wt, int rows, int cols) {
    int i = blockIdx.x * blockDim.x + threadIdx.x;
    if (i < rows * cols) {
        int r = i / cols, c = i % cols;
        Wt[(size_t)c * rows + r] = W[i];
    }
}

// C[M,N] (+)= A[M,K](lda) @ Bt[K,N](ldb) (+ bias)
__global__ __launch_bounds__(256) void sgemm(
    const float* __restrict__ A, int lda,
    const float* __restrict__ Bt, int ldb,
    float* __restrict__ C, int ldc,
    const float* __restrict__ bias,
    int M, int N, int K, int accFlag)
{
    __shared__ float As[16][64];
    __shared__ float Bs[16][64];
    int tid = threadIdx.x;
    int tx = tid & 15, ty = tid >> 4;
    int m0 = blockIdx.y * 64;
    int n0 = blockIdx.x * 64;
    float acc[4][4] = {};

    for (int k0 = 0; k0 < K; k0 += 16) {
#pragma unroll
        for (int v = 0; v < 4; v++) {
            int e = tid + v * 256;
            int kk = e & 15, r = e >> 4;
            int k = k0 + kk;
            float val = 0.0f;
            if (k < K) val = A[(size_t)(m0 + r) * lda + k];
            As[kk][r] = val;
        }
#pragma unroll
        for (int v = 0; v < 4; v++) {
            int e = tid + v * 256;
            int n = e & 63, kk = e >> 6;
            int k = k0 + kk, nn = n0 + n;
            float val = 0.0f;
            if (k < K && nn < N) val = Bt[(size_t)k * ldb + nn];
            Bs[kk][n] = val;
        }
        __syncthreads();
#pragma unroll
        for (int kk = 0; kk < 16; kk++) {
            float a[4], b[4];
#pragma unroll
            for (int i = 0; i < 4; i++) a[i] = As[kk][ty * 4 + i];
#pragma unroll
            for (int j = 0; j < 4; j++) b[j] = Bs[kk][tx * 4 + j];
#pragma unroll
            for (int i = 0; i < 4; i++)
#pragma unroll
                for (int j = 0; j < 4; j++) acc[i][j] += a[i] * b[j];
        }
        __syncthreads();
    }
#pragma unroll
    for (int i = 0; i < 4; i++) {
        int m = m0 + ty * 4 + i;
#pragma unroll
        for (int j = 0; j < 4; j++) {
            int n = n0 + tx * 4 + j;
            if (n < N) {
                float v = acc[i][j];
                if (bias) v += bias[n];
                size_t ci = (size_t)m * ldc + n;
                if (accFlag) v += C[ci];
                C[ci] = v;
            }
        }
    }
}

// h *= exp(-relu(gamma_pre))
__global__ void k_decay(float* __restrict__ h, const float* __restrict__ gam, int n) {
    int i = blockIdx.x * blockDim.x + threadIdx.x;
    if (i < n) h[i] *= expf(-fmaxf(gam[i], 0.0f));
}

// x_c = m*x + (1-m)*x_h ; reduce sum((x-xh)*m)^2 and sum(m) ; write rounded imputation
__global__ void k_xc(const float* __restrict__ values, const float* __restrict__ masks,
                     const float* __restrict__ xh, float* __restrict__ xc,
                     float* __restrict__ outImp, float* __restrict__ acc, int t)
{
    int i = blockIdx.x * blockDim.x + threadIdx.x;
    float ds = 0.0f, ms = 0.0f;
    if (i < Bn * Fn) {
        int b = i / Fn, f = i % Fn;
        size_t gi = ((size_t)b * Tn + t) * Fn + f;
        float x = values[gi], m = masks[gi], xhv = xh[i];
        float d = (x - xhv) * m;
        ds = d * d; ms = m;
        float xcv = m * x + (1.0f - m) * xhv;
        xc[i] = xcv;
        outImp[gi] = rnd6(xcv);
    }
    block_reduce2_atomic(ds, ms, &acc[0], &acc[1]);
}

// enc = tanh(enc_pre) * m   (in place, strided over [B,T,F] at step t)
__global__ void k_encact(float* __restrict__ enc, const float* __restrict__ masks, int t) {
    int i = blockIdx.x * blockDim.x + threadIdx.x;
    if (i < Bn * Fn) {
        int b = i / Fn, f = i % Fn;
        size_t gi = ((size_t)b * Tn + t) * Fn + f;
        enc[gi] = tanhf(enc[gi]) * masks[gi];
    }
}

// LSTM pointwise. If iy != nullptr, add input_y contribution via wiy (rows 0,1 of dec_WihT)
__global__ void k_lstm(const float* __restrict__ gates, float* __restrict__ h, float* __restrict__ c,
                       const float* __restrict__ iy, const float* __restrict__ wiy)
{
    int i = blockIdx.x * blockDim.x + threadIdx.x;
    if (i >= Bn * Hn) return;
    int b = i >> 6, j = i & 63;
    const float* g = gates + (size_t)b * Gn;
    float gi = g[j], gf = g[64 + j], gg = g[128 + j], go = g[192 + j];
    if (iy) {
        float y0 = iy[b * 2], y1 = iy[b * 2 + 1];
        gi += y0 * wiy[j]       + y1 * wiy[Gn + j];
        gf += y0 * wiy[64 + j]  + y1 * wiy[Gn + 64 + j];
        gg += y0 * wiy[128 + j] + y1 * wiy[Gn + 128 + j];
        go += y0 * wiy[192 + j] + y1 * wiy[Gn + 192 + j];
    }
    float cv = sigmoidf_(gf) * c[i] + sigmoidf_(gi) * tanhf(gg);
    float hv = sigmoidf_(go) * tanhf(cv);
    c[i] = cv; h[i] = hv;
}

// y_h = h @ out_W.T + out_b  (thread per (b,o))
__global__ void k_yh(const float* __restrict__ h, const float* __restrict__ outW,
                     const float* __restrict__ outb, float* __restrict__ yh)
{
    int i = blockIdx.x * blockDim.x + threadIdx.x;
    if (i >= Bn * 2) return;
    int b = i >> 1, o = i & 1;
    const float* hr = h + (size_t)b * Hn;
    const float* wr = outW + o * Hn;
    float s = outb[o];
#pragma unroll
    for (int k = 0; k < Hn; k++) s += hr[k] * wr[k];
    yh[i] = s;
}

// first decoder output + y_loss term 0
__global__ void k_dec0(const float* __restrict__ labels, const float* __restrict__ masksy,
                       const float* __restrict__ yh, float* __restrict__ outDec, float* __restrict__ acc)
{
    int i = blockIdx.x * blockDim.x + threadIdx.x;
    float ds = 0.0f, ms = 0.0f;
    if (i < Bn * 2) {
        int b = i >> 1, o = i & 1;
        size_t li = ((size_t)b * Tn + (Tn - 1)) * 2 + o;
        float l0 = labels[li], m0 = masksy[li], y = yh[i];
        float d = (y - l0) * m0;
        ds = d * d; ms = m0;
        float y0 = l0 * m0 + y * (1.0f - m0);
        outDec[li] = rnd6(y0);
    }
    block_reduce2_atomic(ds, ms, &acc[3], &acc[4]);
}

// input_y for step td + write decoded output
__global__ void k_iy(const float* __restrict__ labels, const float* __restrict__ masksy,
                     const float* __restrict__ yh, float* __restrict__ iy,
                     float* __restrict__ outDec, int td)
{
    int i = blockIdx.x * blockDim.x + threadIdx.x;
    if (i >= Bn * 2) return;
    int b = i >> 1, o = i & 1;
    int tr = Tn - 1 - td;
    size_t li = ((size_t)b * Tn + tr) * 2 + o;
    float lv = labels[li], mv = masksy[li];
    float v = lv * mv + yh[i] * (1.0f - mv);
    iy[i] = v;
    outDec[li] = rnd6(v);
}

// y_loss term for step td (after new y_h)
__global__ void k_yloss(const float* __restrict__ labels, const float* __restrict__ masksy,
                        const float* __restrict__ yh, float* __restrict__ acc, int td)
{
    int i = blockIdx.x * blockDim.x + threadIdx.x;
    float ds = 0.0f, ms = 0.0f;
    if (i < Bn * 2) {
        int b = i >> 1, o = i & 1;
        int tr = Tn - 1 - td;
        size_t li = ((size_t)b * Tn + tr) * 2 + o;
        float d = (yh[i] - labels[li]) * masksy[li];
        ds = d * d; ms = masksy[li];
    }
    block_reduce2_atomic(ds, ms, &acc[3], &acc[4]);
}

// attention: energies over T, softmax, context. One block (160 threads) per batch row.
__global__ __launch_bounds__(160) void k_attn(const float* __restrict__ hP, const float* __restrict__ encP,
                                              const float* __restrict__ enc, const float* __restrict__ attv,
                                              float* __restrict__ ctx)
{
    int b = blockIdx.x;
    __shared__ float e[Tn];
    __shared__ float attn[Tn];
    int tid = threadIdx.x;
    int s = tid >> 5, lane = tid & 31;
    if (s < Tn) {
        const float* ep = encP + ((size_t)b * Tn + s) * Hn;
        const float* hp = hP + (size_t)b * Hn;
        float p = attv[lane] * tanhf(hp[lane] + ep[lane])
                + attv[lane + 32] * tanhf(hp[lane + 32] + ep[lane + 32]);
#pragma unroll
        for (int o = 16; o; o >>= 1) p += __shfl_down_sync(0xffffffffu, p, o);
        if (lane == 0) e[s] = p;
    }
    __syncthreads();
    if (tid == 0) {
        float mx = e[0];
#pragma unroll
        for (int k = 1; k < Tn; k++) mx = fmaxf(mx, e[k]);
        float sum = 0.0f;
#pragma unroll
        for (int k = 0; k < Tn; k++) { attn[k] = expf(e[k] - mx); sum += attn[k]; }
        float inv = 1.0f / sum;
#pragma unroll
        for (int k = 0; k < Tn; k++) attn[k] *= inv;
    }
    __syncthreads();
    float a0 = attn[0], a1 = attn[1], a2 = attn[2], a3 = attn[3], a4 = attn[4];
    const float* eb = enc + (size_t)b * Tn * Fn;
    float* cb = ctx + (size_t)b * Fn;
    for (int f = tid; f < Fn; f += 160) {
        cb[f] = a0 * eb[f] + a1 * eb[Fn + f] + a2 * eb[2 * Fn + f]
              + a3 * eb[3 * Fn + f] + a4 * eb[4 * Fn + f];
    }
}

// fold loss partials: acc[di] += acc[si]/denomN/(acc[si+1]+EPS); reset partials
__global__ void k_fold(float* acc, int si, int di, float denomN) {
    if (threadIdx.x == 0) {
        acc[di] += (acc[si] / denomN) / (acc[si + 1] + EPSc);
        acc[si] = 0.0f; acc[si + 1] = 0.0f;
    }
}

__global__ void k_final(const float* acc, float* out) {
    if (threadIdx.x == 0) out[0] = acc[2] / (float)Tn + acc[5] / (float)Tn;
}

// ---------------- host orchestration ----------------
static inline void gemm(const float* A, int lda, const float* Bt, int ldb,
                        float* C, int ldc, const float* bias,
                        int M, int N, int K, int accFlag)
{
    dim3 grid((N + 63) / 64, M / 64);
    sgemm<<<grid, 256>>>(A, lda, Bt, ldb, C, ldc, bias, M, N, K, accFlag);
}

extern "C" void kernel_launch(void* const* d_in, const int* in_sizes, int n_in,
                              void* d_out, int out_size)
{
    const float* values  = (const float*)d_in[0];
    const float* masks   = (const float*)d_in[1];
    const float* deltas  = (const float*)d_in[2];
    const float* labels  = (const float*)d_in[3];
    const float* masks_y = (const float*)d_in[4];
    const float* td_W    = (const float*)d_in[5];
    const float* td_b    = (const float*)d_in[6];
    const float* hist_W  = (const float*)d_in[7];
    const float* hist_b  = (const float*)d_in[8];
    const float* enc_W   = (const float*)d_in[9];
    const float* enc_b   = (const float*)d_in[10];
    const float* rnn_Wih = (const float*)d_in[11];
    const float* rnn_Whh = (const float*)d_in[12];
    const float* rnn_b   = (const float*)d_in[13];
    const float* dec_Wih = (const float*)d_in[14];
    const float* dec_Whh = (const float*)d_in[15];
    const float* dec_b   = (const float*)d_in[16];
    const float* att_W   = (const float*)d_in[17];
    const float* att_b   = (const float*)d_in[18];
    const float* att_v   = (const float*)d_in[19];
    const float* out_W   = (const float*)d_in[20];
    const float* out_b   = (const float*)d_in[21];

    float* out = (float*)d_out;
    float* outImp = out + 1;
    float* outDec = out + 1 + (size_t)Bn * Tn * Fn;

    float* gb = nullptr;
    cudaGetSymbolAddress((void**)&gb, g_buf);

    float* pH      = gb + O_H;
    float* pC      = gb + O_C;
    float* pGam    = gb + O_GAM;
    float* pHP     = gb + O_HP;
    float* pYH     = gb + O_YH;
    float* pIY     = gb + O_IY;
    float* pXH     = gb + O_XH;
    float* pXC     = gb + O_XC;
    float* pCTX    = gb + O_CTX;
    float* pGATES  = gb + O_GATES;
    float* pENC    = gb + O_ENC;
    float* pENCP   = gb + O_ENCP;
    float* pTdWt   = gb + O_TDWT;
    float* pHistWt = gb + O_HISTWT;
    float* pEncWt  = gb + O_ENCWT;
    float* pRnnWihT= gb + O_RNNWIHT;
    float* pRnnWhhT= gb + O_RNNWHHT;
    float* pDecWihT= gb + O_DECWIHT;
    float* pDecWhhT= gb + O_DECWHHT;
    float* pAttWt  = gb + O_ATTWT;
    float* pAcc    = gb + O_ACC;

    // ---- weight transposes (W[out,in] -> Wt[in,out]) ----
    {
        auto tp = [](const float* W, float* Wt, int rows, int cols) {
            int n = rows * cols;
            k_transpose<<<(n + 255) / 256, 256>>>(W, Wt, rows, cols);
        };
        tp(td_W,    pTdWt,    Hn, Fn);          // [64,923]  -> [923,64]
        tp(hist_W,  pHistWt,  Fn, Hn);          // [923,64]  -> [64,923]
        tp(enc_W,   pEncWt,   Fn, Hn);          // [923,64]  -> [64,923]
        tp(rnn_Wih, pRnnWihT, Gn, 2 * Fn);      // [256,1846]-> [1846,256]
        tp(rnn_Whh, pRnnWhhT, Gn, Hn);          // [256,64]  -> [64,256]
        tp(dec_Wih, pDecWihT, Gn, Fn + 2);      // [256,925] -> [925,256]
        tp(dec_Whh, pDecWhhT, Gn, Hn);          // [256,64]  -> [64,256]
        tp(att_W,   pAttWt,   Hn, Fn + Hn);     // [64,987]  -> [987,64]
    }

    // ---- init state & accumulators ----
    k_zero<<<(unsigned)((2 * SZ_H + 255) / 256), 256>>>(pH, 2 * SZ_H); // h and c contiguous
    k_zero<<<1, 32>>>(pAcc, 16);

    const int nBH = Bn * Hn, nBF = Bn * Fn, nB2 = Bn * 2;
    const int gBH = (nBH + 255) / 256, gBF = (nBF + 255) / 256, gB2 = (nB2 + 255) / 256;

    // ================= encoder =================
    for (int t = 0; t < Tn; t++) {
        // gamma_pre = deltas_t @ tdWt + td_b
        gemm(deltas + (size_t)t * Fn, Tn * Fn, pTdWt, Hn, pGam, Hn, td_b, Bn, Hn, Fn, 0);
        k_decay<<<gBH, 256>>>(pH, pGam, nBH);
        // x_h = h @ histWt + hist_b
        gemm(pH, Hn, pHistWt, Fn, pXH, Fn, hist_b, Bn, Fn, Hn, 0);
        // x_c, imputation output, x-loss partials
        k_xc<<<gBF, 256>>>(values, masks, pXH, pXC, outImp, pAcc, t);
        k_fold<<<1, 32>>>(pAcc, 0, 2, (float)Bn * (float)Fn);
        // enc_pre = h @ encWt + enc_b  -> enc_out[:,t,:]
        gemm(pH, Hn, pEncWt, Fn, pENC + (size_t)t * Fn, Tn * Fn, enc_b, Bn, Fn, Hn, 0);
        k_encact<<<gBF, 256>>>(pENC, masks, t);
        // gates = xc @ WihT[:923] + rnn_b ; += m_t @ WihT[923:] ; += h @ WhhT
        gemm(pXC, Fn, pRnnWihT, Gn, pGATES, Gn, rnn_b, Bn, Gn, Fn, 0);
        gemm(masks + (size_t)t * Fn, Tn * Fn, pRnnWihT + (size_t)Fn * Gn, Gn, pGATES, Gn, nullptr, Bn, Gn, Fn, 1);
        gemm(pH, Hn, pRnnWhhT, Gn, pGATES, Gn, nullptr, Bn, Gn, Hn, 1);
        k_lstm<<<gBH, 256>>>(pGATES, pH, pC, nullptr, nullptr);
    }

    // y_h from encoder-final h
    k_yh<<<gB2, 256>>>(pH, out_W, out_b, pYH);
    k_dec0<<<gB2, 256>>>(labels, masks_y, pYH, outDec, pAcc);
    k_fold<<<1, 32>>>(pAcc, 3, 5, (float)Bn * 2.0f);

    // encP = enc_out @ attW[:,64:].T + att_b  (once)
    gemm(pENC, Fn, pAttWt + (size_t)Hn * Hn, Hn, pENCP, Hn, att_b, Bn * Tn, Hn, Fn, 0);

    // ================= decoder =================
    for (int td = 1; td < Tn; td++) {
        k_iy<<<gB2, 256>>>(labels, masks_y, pYH, pIY, outDec, td);
        // hP = h @ attW[:,:64].T
        gemm(pH, Hn, pAttWt, Hn, pHP, Hn, nullptr, Bn, Hn, Hn, 0);
        k_attn<<<Bn, 160>>>(pHP, pENCP, pENC, att_v, pCTX);
        // gates = ctx @ decWihT[2:] + dec_b ; += h @ decWhhT ; input_y folded in k_lstm
        gemm(pCTX, Fn, pDecWihT + 2 * Gn, Gn, pGATES, Gn, dec_b, Bn, Gn, Fn, 0);
        gemm(pH, Hn, pDecWhhT, Gn, pGATES, Gn, nullptr, Bn, Gn, Hn, 1);
        k_lstm<<<gBH, 256>>>(pGATES, pH, pC, pIY, pDecWihT);
        k_yh<<<gB2, 256>>>(pH, out_W, out_b, pYH);
        k_yloss<<<gB2, 256>>>(labels, masks_y, pYH, pAcc, td);
        k_fold<<<1, 32>>>(pAcc, 3, 5, (float)Bn * 2.0f);
    }

    k_final<<<1, 32>>>(pAcc, out);
}

// round 2
// speedup vs baseline: 1.5893x; 1.5893x over previous
#include <cuda_runtime.h>
#include <math.h>
#include <stdint.h>

#define Bn 8192
#define Tn 5
#define Fn 923
#define Hn 64
#define Gn 256
#define EPSc 1e-5f

typedef unsigned long long ull;

// ---------------- scratch layout ----------------
constexpr size_t AL(size_t x) { return (x + 15) & ~(size_t)15; }

constexpr size_t O_H      = 0;
constexpr size_t O_C      = AL(O_H + (size_t)Bn * Hn);
constexpr size_t O_YH     = AL(O_C + (size_t)Bn * Hn);
constexpr size_t O_ACC    = AL(O_YH + (size_t)Bn * 2);
constexpr size_t O_XCAT   = AL(O_ACC + 32);                       // [B, 992]
constexpr size_t O_GATES  = AL(O_XCAT + (size_t)Bn * 992);        // [B, 256]
constexpr size_t O_ENC    = AL(O_GATES + (size_t)Bn * Gn);        // [B,T,923]
constexpr size_t O_ENCPG  = AL(O_ENC + (size_t)Bn * Tn * Fn);     // [B,T,320]
constexpr size_t O_TDPRE  = AL(O_ENCPG + (size_t)Bn * Tn * 320);  // [B,T,64]
constexpr size_t O_MASKG  = AL(O_TDPRE + (size_t)Bn * Tn * Hn);   // [B,T,256]
constexpr size_t O_TDWT   = AL(O_MASKG + (size_t)Bn * Tn * Gn);   // [923,64]
constexpr size_t O_WHE    = AL(O_TDWT + (size_t)Fn * Hn);         // [64,1846]
constexpr size_t O_BHE    = AL(O_WHE + (size_t)Hn * 2 * Fn);      // [1846]
constexpr size_t O_WCOMB  = AL(O_BHE + 2 * Fn);                   // [987,256]
constexpr size_t O_MASKW  = AL(O_WCOMB + (size_t)987 * Gn);       // [923,256]
constexpr size_t O_WENC2  = AL(O_MASKW + (size_t)Fn * Gn);        // [923,320]
constexpr size_t O_B2     = AL(O_WENC2 + (size_t)Fn * 320);       // [320]
constexpr size_t O_ATTWHT = AL(O_B2 + 320);                       // [64,64]
constexpr size_t O_DWHHT  = AL(O_ATTWHT + Hn * Hn);               // [64,256]
constexpr size_t TOTAL_FLOATS = AL(O_DWHHT + (size_t)Hn * Gn) + 16;

static __device__ float g_buf[TOTAL_FLOATS];

// ---------------- helpers ----------------
__device__ __forceinline__ float sigmoidf_(float x) { return 1.0f / (1.0f + expf(-x)); }
__device__ __forceinline__ float rnd6(float v) { return rintf(v * 1e6f) / 1e6f; }

__device__ __forceinline__ ull pk2(float lo, float hi) {
    ull r; asm("mov.b64 %0, {%1, %2};" : "=l"(r) : "f"(lo), "f"(hi)); return r;
}
__device__ __forceinline__ void upk2(ull v, float& lo, float& hi) {
    asm("mov.b64 {%0, %1}, %2;" : "=f"(lo), "=f"(hi) : "l"(v));
}
__device__ __forceinline__ void fma2(ull& d, ull a, ull b) {
    asm("fma.rn.f32x2 %0, %1, %2, %0;" : "+l"(d) : "l"(a), "l"(b));
}

__device__ __forceinline__ void block_reduce2_atomic(float v0, float v1, float* a0, float* a1) {
    __shared__ float s0[32], s1[32];
    int lane = threadIdx.x & 31, w = threadIdx.x >> 5;
#pragma unroll
    for (int o = 16; o; o >>= 1) {
        v0 += __shfl_down_sync(0xffffffffu, v0, o);
        v1 += __shfl_down_sync(0xffffffffu, v1, o);
    }
    if (lane == 0) { s0[w] = v0; s1[w] = v1; }
    __syncthreads();
    if (w == 0) {
        int nw = (blockDim.x + 31) >> 5;
        v0 = (lane < nw) ? s0[lane] : 0.0f;
        v1 = (lane < nw) ? s1[lane] : 0.0f;
#pragma unroll
        for (int o = 16; o; o >>= 1) {
            v0 += __shfl_down_sync(0xffffffffu, v0, o);
            v1 += __shfl_down_sync(0xffffffffu, v1, o);
        }
        if (lane == 0) { atomicAdd(a0, v0); atomicAdd(a1, v1); }
    }
}

// ---------------- init / pack kernels ----------------
__global__ void k_zero(float* p, int n) {
    int i = blockIdx.x * blockDim.x + threadIdx.x;
    if (i < n) p[i] = 0.0f;
}
__global__ void k_zerocols(float* xcat) {  // zero cols 923..991 of xcat
    int i = blockIdx.x * blockDim.x + threadIdx.x;
    if (i < Bn * 69) { int b = i / 69, j = i % 69; xcat[(size_t)b * 992 + 923 + j] = 0.0f; }
}
__global__ void k_pack_tdW(const float* __restrict__ W, float* __restrict__ dst) {
    int i = blockIdx.x * blockDim.x + threadIdx.x;
    if (i < Fn * Hn) { int k = i / Hn, j = i % Hn; dst[i] = W[j * Fn + k]; }
}
__global__ void k_pack_whe(const float* __restrict__ histW, const float* __restrict__ encW,
                           const float* __restrict__ histb, const float* __restrict__ encb,
                           float* __restrict__ dst, float* __restrict__ bias) {
    int i = blockIdx.x * blockDim.x + threadIdx.x;
    if (i < Hn * 2 * Fn) {
        int k = i / (2 * Fn), n = i % (2 * Fn);
        dst[i] = (n < Fn) ? histW[n * Hn + k] : encW[(n - Fn) * Hn + k];
    }
    if (i < 2 * Fn) bias[i] = (i < Fn) ? histb[i] : encb[i - Fn];
}
__global__ void k_pack_wcomb(const float* __restrict__ Wih, const float* __restrict__ Whh,
                             float* __restrict__ dst) {
    int i = blockIdx.x * blockDim.x + threadIdx.x;
    if (i < 987 * Gn) {
        int k = i / Gn, j = i % Gn;
        dst[i] = (k < Fn) ? Wih[j * (2 * Fn) + k] : Whh[j * Hn + (k - Fn)];
    }
}
__global__ void k_pack_maskW(const float* __restrict__ Wih, float* __restrict__ dst) {
    int i = blockIdx.x * blockDim.x + threadIdx.x;
    if (i < Fn * Gn) { int k = i / Gn, j = i % Gn; dst[i] = Wih[j * (2 * Fn) + Fn + k]; }
}
__global__ void k_pack_wenc2(const float* __restrict__ attW, const float* __restrict__ decWih,
                             const float* __restrict__ attb, const float* __restrict__ decb,
                             float* __restrict__ dst, float* __restrict__ bias) {
    int i = blockIdx.x * blockDim.x + threadIdx.x;
    if (i < Fn * 320) {
        int k = i / 320, n = i % 320;
        dst[i] = (n < Hn) ? attW[n * 987 + Hn + k] : decWih[(n - Hn) * 925 + 2 + k];
    }
    if (i < 320) bias[i] = (i < Hn) ? attb[i] : decb[i - Hn];
}
__global__ void k_pack_attWhT(const float* __restrict__ attW, float* __restrict__ dst) {
    int i = blockIdx.x * blockDim.x + threadIdx.x;
    if (i < Hn * Hn) { int k = i / Hn, j = i % Hn; dst[i] = attW[j * 987 + k]; }
}
__global__ void k_pack_dWhhT(const float* __restrict__ Whh, float* __restrict__ dst) {
    int i = blockIdx.x * blockDim.x + threadIdx.x;
    if (i < Hn * Gn) { int k = i / Gn, j = i % Gn; dst[i] = Whh[j * Hn + k]; }
}

// ---------------- SGEMM with FFMA2, 128x64 block, 8x4/thread, ping-pong ----------------
// EPI 0: C = acc + bias ; EPI 1: C = acc + add[m*addLd+n] ; EPI 2: histenc fused epilogue
template<int EPI>
__global__ __launch_bounds__(256) void sgemm(
    const float* __restrict__ A, int lda,
    const float* __restrict__ Bt, int ldb,
    float* __restrict__ C, int ldc,
    const float* __restrict__ bias,
    const float* __restrict__ add, int addLd,
    int N, int K,
    const float* __restrict__ values, const float* __restrict__ masks,
    float* __restrict__ outImp, float* __restrict__ xcat,
    float* __restrict__ enc, float* __restrict__ accp, int t)
{
    __shared__ float As[2][16][128];
    __shared__ float Bs[2][16][64];
    const int tid = threadIdx.x;
    const int m0 = blockIdx.y * 128, n0 = blockIdx.x * 64;
    const int ar = tid >> 1, akh = (tid & 1) * 8;
    const int bk = tid >> 4, bn = (tid & 15) * 4;
    const int ty = tid >> 4, tx = tid & 15;
    const int NT = (K + 15) >> 4;

    float Ar[8], Br[4];
    // prologue: tile 0
    {
        const float* ap = A + (size_t)(m0 + ar) * lda + akh;
#pragma unroll
        for (int i = 0; i < 8; i++) { int k = akh + i; Ar[i] = (k < K) ? ap[i] : 0.0f; }
#pragma unroll
        for (int i = 0; i < 4; i++) {
            int n = n0 + bn + i;
            Br[i] = (bk < K && n < N) ? Bt[(size_t)bk * ldb + n] : 0.0f;
        }
#pragma unroll
        for (int i = 0; i < 8; i++) As[0][akh + i][ar] = Ar[i];
#pragma unroll
        for (int i = 0; i < 4; i++) Bs[0][bk][bn + i] = Br[i];
    }
    __syncthreads();

    ull acc[4][4];
#pragma unroll
    for (int i = 0; i < 4; i++)
#pragma unroll
        for (int j = 0; j < 4; j++) acc[i][j] = 0ULL;

    int cur = 0;
    for (int t0 = 0; t0 < NT; t0++) {
        const bool pf = (t0 + 1 < NT);
        if (pf) {
            const int k0n = (t0 + 1) << 4;
            const float* ap = A + (size_t)(m0 + ar) * lda + k0n + akh;
#pragma unroll
            for (int i = 0; i < 8; i++) { int k = k0n + akh + i; Ar[i] = (k < K) ? ap[i] : 0.0f; }
            const int kb = k0n + bk;
#pragma unroll
            for (int i = 0; i < 4; i++) {
                int n = n0 + bn + i;
                Br[i] = (kb < K && n < N) ? Bt[(size_t)kb * ldb + n] : 0.0f;
            }
        }
#pragma unroll
        for (int kk = 0; kk < 16; kk++) {
            ull a2[4];
#pragma unroll
            for (int i2 = 0; i2 < 4; i2++)
                a2[i2] = *reinterpret_cast<const ull*>(&As[cur][kk][ty * 8 + i2 * 2]);
#pragma unroll
            for (int j = 0; j < 4; j++) {
                float bv = Bs[cur][kk][tx * 4 + j];
                ull bd = pk2(bv, bv);
#pragma unroll
                for (int i2 = 0; i2 < 4; i2++) fma2(acc[i2][j], a2[i2], bd);
            }
        }
        if (pf) {
#pragma unroll
            for (int i = 0; i < 8; i++) As[cur ^ 1][akh + i][ar] = Ar[i];
#pragma unroll
            for (int i = 0; i < 4; i++) Bs[cur ^ 1][bk][bn + i] = Br[i];
        }
        __syncthreads();
        cur ^= 1;
    }

    // epilogue
    float ds = 0.0f, ms = 0.0f;
#pragma unroll
    for (int i2 = 0; i2 < 4; i2++) {
#pragma unroll
        for (int j = 0; j < 4; j++) {
            float lo, hi; upk2(acc[i2][j], lo, hi);
#pragma unroll
            for (int h2 = 0; h2 < 2; h2++) {
                float v = h2 ? hi : lo;
                int m = m0 + ty * 8 + i2 * 2 + h2;
                int n = n0 + tx * 4 + j;
                if (n < N) {
                    if (EPI == 0) {
                        C[(size_t)m * ldc + n] = v + (bias ? bias[n] : 0.0f);
                    } else if (EPI == 1) {
                        C[(size_t)m * ldc + n] = v + add[(size_t)m * addLd + n];
                    } else {
                        v += bias[n];
                        if (n < Fn) {
                            size_t gi = ((size_t)m * Tn + t) * Fn + n;
                            float x = values[gi], mm = masks[gi];
                            float d = (x - v) * mm;
                            ds += d * d; ms += mm;
                            float xcv = fmaf(mm, x - v, v);
                            xcat[(size_t)m * 992 + n] = xcv;
                            outImp[gi] = rnd6(xcv);
                        } else {
                            int f = n - Fn;
                            size_t gi = ((size_t)m * Tn + t) * Fn + f;
                            enc[gi] = tanhf(v) * masks[gi];
                        }
                    }
                }
            }
        }
    }
    if (EPI == 2) block_reduce2_atomic(ds, ms, accp + 2 * t, accp + 2 * t + 1);
}

// ---------------- LSTM pointwise (encoder), with gamma-decay for next step ----------------
__global__ void k_lstm(const float* __restrict__ gates, float* __restrict__ h, float* __restrict__ c,
                       float* __restrict__ xcat, const float* __restrict__ tdPre, int t)
{
    int i = blockIdx.x * blockDim.x + threadIdx.x;
    if (i >= Bn * Hn) return;
    int b = i >> 6, j = i & 63;
    const float* g = gates + (size_t)b * Gn;
    float cv = sigmoidf_(g[64 + j]) * c[i] + sigmoidf_(g[j]) * tanhf(g[128 + j]);
    float hv = sigmoidf_(g[192 + j]) * tanhf(cv);
    c[i] = cv;
    if (t < Tn - 1) {
        float gm = expf(-fmaxf(tdPre[((size_t)b * Tn + t + 1) * Hn + j], 0.0f));
        hv *= gm;
        xcat[(size_t)b * 992 + Fn + j] = hv;
    }
    h[i] = hv;
}

// ---------------- y_h from final encoder h + first decoder output + y-loss[0] ----------------
__global__ void k_yh0(const float* __restrict__ pH, const float* __restrict__ outW,
                      const float* __restrict__ outb, const float* __restrict__ labels,
                      const float* __restrict__ masky, float* __restrict__ pYH,
                      float* __restrict__ outDec, float* __restrict__ accp)
{
    int gid = blockIdx.x * blockDim.x + threadIdx.x;  // 16384
    int b = gid >> 1, o = gid & 1;
    const float* hr = pH + (size_t)b * Hn;
    const float* wr = outW + o * Hn;
    float s = outb[o];
#pragma unroll
    for (int k = 0; k < Hn; k++) s += hr[k] * wr[k];
    pYH[gid] = s;
    size_t li = ((size_t)b * Tn + (Tn - 1)) * 2 + o;
    float l0 = labels[li], m0 = masky[li];
    float d = (s - l0) * m0;
    outDec[li] = rnd6(l0 * m0 + s * (1.0f - m0));
    block_reduce2_atomic(d * d, m0, accp + 10, accp + 11);
}

// ---------------- fused decoder step ----------------
__global__ __launch_bounds__(256) void k_decstep(
    const float* __restrict__ labels, const float* __restrict__ masky,
    float* __restrict__ pH, float* __restrict__ pC, float* __restrict__ pYH,
    const float* __restrict__ encPG, const float* __restrict__ attWhT,
    const float* __restrict__ dWhhT, const float* __restrict__ decWih,
    const float* __restrict__ attv, const float* __restrict__ outW,
    const float* __restrict__ outb, float* __restrict__ outDec,
    float* __restrict__ accp, int td)
{
    int b = blockIdx.x, tid = threadIdx.x;
    __shared__ float sh[64], shp[64], siy[2], se[5], sattn[5], sg[256], shn[64], syh[2];
    const int tr = Tn - 1 - td;

    if (tid < 64) sh[tid] = pH[(size_t)b * Hn + tid];
    if (tid >= 64 && tid < 66) {
        int o = tid - 64;
        size_t li = ((size_t)b * Tn + tr) * 2 + o;
        float lv = labels[li], mv = masky[li];
        float v = lv * mv + pYH[b * 2 + o] * (1.0f - mv);
        siy[o] = v;
        outDec[li] = rnd6(v);
    }
    __syncthreads();

    if (tid < 64) {
        float s = 0.0f;
#pragma unroll 16
        for (int k = 0; k < 64; k++) s += sh[k] * attWhT[k * 64 + tid];
        shp[tid] = s;
    }
    __syncthreads();

    int w = tid >> 5, lane = tid & 31;
    if (w < Tn) {
        const float* ep = encPG + ((size_t)b * Tn + w) * 320;
        float p = attv[lane] * tanhf(shp[lane] + ep[lane])
                + attv[lane + 32] * tanhf(shp[lane + 32] + ep[lane + 32]);
#pragma unroll
        for (int o = 16; o; o >>= 1) p += __shfl_down_sync(0xffffffffu, p, o);
        if (lane == 0) se[w] = p;
    }
    __syncthreads();
    if (tid == 0) {
        float mx = se[0];
#pragma unroll
        for (int k = 1; k < Tn; k++) mx = fmaxf(mx, se[k]);
        float sum = 0.0f;
#pragma unroll
        for (int k = 0; k < Tn; k++) { sattn[k] = expf(se[k] - mx); sum += sattn[k]; }
        float inv = 1.0f / sum;
#pragma unroll
        for (int k = 0; k < Tn; k++) sattn[k] *= inv;
    }
    __syncthreads();

    {   // gates[j], j = tid : context part + Whh part + input_y part (dec_b folded via encPG bias)
        const float* eg = encPG + (size_t)b * Tn * 320 + 64;
        float g = sattn[0] * eg[tid] + sattn[1] * eg[320 + tid] + sattn[2] * eg[640 + tid]
                + sattn[3] * eg[960 + tid] + sattn[4] * eg[1280 + tid];
#pragma unroll 16
        for (int k = 0; k < 64; k++) g += sh[k] * dWhhT[k * 256 + tid];
        g += siy[0] * decWih[tid * 925 + 0] + siy[1] * decWih[tid * 925 + 1];
        sg[tid] = g;
    }
    __syncthreads();

    if (tid < 64) {
        float cv = sigmoidf_(sg[64 + tid]) * pC[(size_t)b * Hn + tid]
                 + sigmoidf_(sg[tid]) * tanhf(sg[128 + tid]);
        float hv = sigmoidf_(sg[192 + tid]) * tanhf(cv);
        pC[(size_t)b * Hn + tid] = cv;
        pH[(size_t)b * Hn + tid] = hv;
        shn[tid] = hv;
    }
    __syncthreads();

    if (w < 2) {
        float p = shn[lane] * outW[w * 64 + lane] + shn[lane + 32] * outW[w * 64 + lane + 32];
#pragma unroll
        for (int o = 16; o; o >>= 1) p += __shfl_down_sync(0xffffffffu, p, o);
        if (lane == 0) { float yv = p + outb[w]; syh[w] = yv; pYH[b * 2 + w] = yv; }
    }
    __syncthreads();

    float ds = 0.0f, ms = 0.0f;
    if (tid < 2) {
        size_t li = ((size_t)b * Tn + tr) * 2 + tid;
        float d = (syh[tid] - labels[li]) * masky[li];
        ds = d * d; ms = masky[li];
    }
    block_reduce2_atomic(ds, ms, accp + 10 + 2 * td, accp + 11 + 2 * td);
}

__global__ void k_final(const float* __restrict__ acc, float* __restrict__ out) {
    if (threadIdx.x == 0) {
        float xl = 0.0f, yl = 0.0f;
#pragma unroll
        for (int t = 0; t < Tn; t++)
            xl += (acc[2 * t] / ((float)Bn * (float)Fn)) / (acc[2 * t + 1] + EPSc);
#pragma unroll
        for (int td = 0; td < Tn; td++)
            yl += (acc[10 + 2 * td] / ((float)Bn * 2.0f)) / (acc[11 + 2 * td] + EPSc);
        out[0] = xl / (float)Tn + yl / (float)Tn;
    }
}

// ---------------- host orchestration ----------------
static inline void gemm_bias(const float* A, int lda, const float* Bt, int ldb,
                             float* C, int ldc, const float* bias, int M, int N, int K) {
    dim3 g((N + 63) / 64, M / 128);
    sgemm<0><<<g, 256>>>(A, lda, Bt, ldb, C, ldc, bias, nullptr, 0, N, K,
                         nullptr, nullptr, nullptr, nullptr, nullptr, nullptr, 0);
}
static inline void gemm_add(const float* A, int lda, const float* Bt, int ldb,
                            float* C, int ldc, const float* add, int addLd, int M, int N, int K) {
    dim3 g((N + 63) / 64, M / 128);
    sgemm<1><<<g, 256>>>(A, lda, Bt, ldb, C, ldc, nullptr, add, addLd, N, K,
                         nullptr, nullptr, nullptr, nullptr, nullptr, nullptr, 0);
}
static inline void gemm_histenc(const float* A, int lda, const float* Bt, int ldb,
                                const float* bias, int M, int N, int K,
                                const float* values, const float* masks,
                                float* outImp, float* xcat, float* enc, float* accp, int t) {
    dim3 g((N + 63) / 64, M / 128);
    sgemm<2><<<g, 256>>>(A, lda, Bt, ldb, nullptr, 0, bias, nullptr, 0, N, K,
                         values, masks, outImp, xcat, enc, accp, t);
}

extern "C" void kernel_launch(void* const* d_in, const int* in_sizes, int n_in,
                              void* d_out, int out_size)
{
    const float* values  = (const float*)d_in[0];
    const float* masks   = (const float*)d_in[1];
    const float* deltas  = (const float*)d_in[2];
    const float* labels  = (const float*)d_in[3];
    const float* masks_y = (const float*)d_in[4];
    const float* td_W    = (const float*)d_in[5];
    const float* td_b    = (const float*)d_in[6];
    const float* hist_W  = (const float*)d_in[7];
    const float* hist_b  = (const float*)d_in[8];
    const float* enc_W   = (const float*)d_in[9];
    const float* enc_b   = (const float*)d_in[10];
    const float* rnn_Wih = (const float*)d_in[11];
    const float* rnn_Whh = (const float*)d_in[12];
    const float* rnn_b   = (const float*)d_in[13];
    const float* dec_Wih = (const float*)d_in[14];
    const float* dec_Whh = (const float*)d_in[15];
    const float* dec_b   = (const float*)d_in[16];
    const float* att_W   = (const float*)d_in[17];
    const float* att_b   = (const float*)d_in[18];
    const float* att_v   = (const float*)d_in[19];
    const float* out_W   = (const float*)d_in[20];
    const float* out_b   = (const float*)d_in[21];

    float* out = (float*)d_out;
    float* outImp = out + 1;
    float* outDec = out + 1 + (size_t)Bn * Tn * Fn;

    float* gb = nullptr;
    cudaGetSymbolAddress((void**)&gb, g_buf);

    float* pH     = gb + O_H;
    float* pC     = gb + O_C;
    float* pYH    = gb + O_YH;
    float* pAcc   = gb + O_ACC;
    float* pXCAT  = gb + O_XCAT;
    float* pGATES = gb + O_GATES;
    float* pENC   = gb + O_ENC;
    float* pENCPG = gb + O_ENCPG;
    float* pTDPRE = gb + O_TDPRE;
    float* pMASKG = gb + O_MASKG;
    float* pTdWt  = gb + O_TDWT;
    float* pWHE   = gb + O_WHE;
    float* pBHE   = gb + O_BHE;
    float* pWCOMB = gb + O_WCOMB;
    float* pMASKW = gb + O_MASKW;
    float* pWENC2 = gb + O_WENC2;
    float* pB2    = gb + O_B2;
    float* pATTWHT= gb + O_ATTWHT;
    float* pDWHHT = gb + O_DWHHT;

    // ---- packs ----
    k_pack_tdW  <<<(Fn * Hn + 255) / 256, 256>>>(td_W, pTdWt);
    k_pack_whe  <<<(Hn * 2 * Fn + 255) / 256, 256>>>(hist_W, enc_W, hist_b, enc_b, pWHE, pBHE);
    k_pack_wcomb<<<(987 * Gn + 255) / 256, 256>>>(rnn_Wih, rnn_Whh, pWCOMB);
    k_pack_maskW<<<(Fn * Gn + 255) / 256, 256>>>(rnn_Wih, pMASKW);
    k_pack_wenc2<<<(Fn * 320 + 255) / 256, 256>>>(att_W, dec_Wih, att_b, dec_b, pWENC2, pB2);
    k_pack_attWhT<<<(Hn * Hn + 255) / 256, 256>>>(att_W, pATTWHT);
    k_pack_dWhhT<<<(Hn * Gn + 255) / 256, 256>>>(dec_Whh, pDWHHT);

    // ---- init ----
    k_zero<<<(2 * Bn * Hn + 255) / 256, 256>>>(pH, 2 * Bn * Hn);  // h & c contiguous
    k_zero<<<1, 32>>>(pAcc, 32);
    k_zerocols<<<(Bn * 69 + 255) / 256, 256>>>(pXCAT);

    // ---- upfront batched GEMMs (off critical path) ----
    // tdPre[B*T,64] = deltas @ tdWt + td_b
    gemm_bias(deltas, Fn, pTdWt, Hn, pTDPRE, Hn, td_b, Bn * Tn, Hn, Fn);
    // maskG[B*T,256] = masks @ maskW + rnn_b
    gemm_bias(masks, Fn, pMASKW, Gn, pMASKG, Gn, rnn_b, Bn * Tn, Gn, Fn);

    // ---- encoder ----
    for (int t = 0; t < Tn; t++) {
        // fused hist+enc GEMM: [B,64] @ [64,1846]; epilogue -> xcat, outImp, enc, x-loss
        gemm_histenc(pH, Hn, pWHE, 2 * Fn, pBHE, Bn, 2 * Fn, Hn,
                     values, masks, outImp, pXCAT, pENC, pAcc, t);
        // gates = [xc|h] @ wcomb + maskG[b,t]
        gemm_add(pXCAT, 992, pWCOMB, Gn, pGATES, Gn, pMASKG + (size_t)t * Gn, Tn * Gn,
                 Bn, Gn, 987);
        k_lstm<<<(Bn * Hn + 255) / 256, 256>>>(pGATES, pH, pC, pXCAT, pTDPRE, t);
    }

    // ---- y_h + first decoder output ----
    k_yh0<<<Bn * 2 / 128, 128>>>(pH, out_W, out_b, labels, masks_y, pYH, outDec, pAcc);

    // encPG[B*T,320] = enc @ [attWe | decW_ctx] + [att_b | dec_b]
    gemm_bias(pENC, Fn, pWENC2, 320, pENCPG, 320, pB2, Bn * Tn, 320, Fn);

    // ---- decoder (fully fused per step) ----
    for (int td = 1; td < Tn; td++) {
        k_decstep<<<Bn, 256>>>(labels, masks_y, pH, pC, pYH, pENCPG, pATTWHT,
                               pDWHHT, dec_Wih, att_v, out_W, out_b, outDec, pAcc, td);
    }

    k_final<<<1, 32>>>(pAcc, out);
}